// round 15
// baseline (speedup 1.0000x reference)
#include <cuda_runtime.h>
#include <math.h>

#define HDIM 1024
#define SDIM 2048
#define VDIM 50257
#define IN0  2048
#define NMEGA 512            // mega-kernel blocks (all co-resident: >=4/SM * 148)
#define SCH  128             // context s-chunks (16 rows each)
#define NBLK_L 6283          // ceil(VDIM/8) logits blocks

// ---- scratch (no allocations allowed) ----
__device__ float g_h0[HDIM];
__device__ float g_cat[2 * HDIM];     // [h1, context]
__device__ float g_energies[SDIM];
__device__ float g_em[NMEGA];         // per-block energy max (4 rows each)
__device__ float g_es[NMEGA];         // per-block energy sumexp
__device__ float g_ctx_part[SCH * HDIM];
__device__ float g_logits[VDIM];
__device__ float g_red_m[NBLK_L];
__device__ float g_red_s[NBLK_L];
// grid-barrier state (zero-init; self-resetting per launch)
__device__ unsigned g_arr[4], g_rel[4], g_dep[4];

__device__ __forceinline__ float warpSum(float v) {
#pragma unroll
    for (int o = 16; o > 0; o >>= 1) v += __shfl_down_sync(0xffffffffu, v, o);
    return v;
}
__device__ __forceinline__ float dot4(float4 a, float4 b) {
    return a.x * b.x + a.y * b.y + a.z * b.z + a.w * b.w;
}
__device__ __forceinline__ void msMerge(float& M, float& S, float m2, float s2) {
    float Mn = fmaxf(M, m2);
    S = S * expf(M - Mn) + s2 * expf(m2 - Mn);
    M = Mn;
}

// grid-wide barrier: arrive/release/depart; last departer resets all three.
// Safe iff all NMEGA blocks are co-resident (guaranteed by launch_bounds + resources).
__device__ __forceinline__ void gridBarrier(int i) {
    __syncthreads();
    if (threadIdx.x == 0) {
        __threadfence();
        unsigned old = atomicAdd(&g_arr[i], 1u);
        if (old == NMEGA - 1) atomicExch(&g_rel[i], 1u);
        while (atomicAdd(&g_rel[i], 0u) == 0u) __nanosleep(64);
        __threadfence();
        unsigned d = atomicAdd(&g_dep[i], 1u);
        if (d == NMEGA - 1) {
            atomicExch(&g_arr[i], 0u);
            atomicExch(&g_dep[i], 0u);
            atomicExch(&g_rel[i], 0u);
        }
    }
    __syncthreads();
}

// ---- GRU unit helper: one hidden unit j for one layer ----
template <int IN>
__device__ __forceinline__ void gru_unit(
        int j, int tid,
        const float* __restrict__ Wih, const float* __restrict__ Whh,
        const float* __restrict__ bih, const float* __restrict__ bhh,
        const float* __restrict__ hprev,
        const float4* xs, const float4* hs, float* s_red,
        float* gout, float* dout_h) {
    const float4* wr = (const float4*)(Wih + (size_t)j * IN);
    const float4* wz = (const float4*)(Wih + (size_t)(HDIM + j) * IN);
    const float4* wn = (const float4*)(Wih + (size_t)(2 * HDIM + j) * IN);
    const float4* ur = (const float4*)(Whh + (size_t)j * HDIM);
    const float4* uz = (const float4*)(Whh + (size_t)(HDIM + j) * HDIM);
    const float4* un = (const float4*)(Whh + (size_t)(2 * HDIM + j) * HDIM);

    float s0, s1, s2, s3, s4, s5;
    if (IN == 2048) {
        float4 r0a = __ldcs(wr + tid), r0b = __ldcs(wr + tid + 256);
        float4 r1a = __ldcs(wz + tid), r1b = __ldcs(wz + tid + 256);
        float4 r2a = __ldcs(wn + tid), r2b = __ldcs(wn + tid + 256);
        float4 r3  = __ldcs(ur + tid);
        float4 r4  = __ldcs(uz + tid);
        float4 r5  = __ldcs(un + tid);
        float4 xa = xs[tid], xb = xs[tid + 256], hv = hs[tid];
        s0 = dot4(r0a, xa) + dot4(r0b, xb);
        s1 = dot4(r1a, xa) + dot4(r1b, xb);
        s2 = dot4(r2a, xa) + dot4(r2b, xb);
        s3 = dot4(r3, hv); s4 = dot4(r4, hv); s5 = dot4(r5, hv);
    } else {
        float4 r0 = __ldcs(wr + tid);
        float4 r1 = __ldcs(wz + tid);
        float4 r2 = __ldcs(wn + tid);
        float4 r3 = __ldcs(ur + tid);
        float4 r4 = __ldcs(uz + tid);
        float4 r5 = __ldcs(un + tid);
        float4 xa = xs[tid], hv = hs[tid];
        s0 = dot4(r0, xa); s1 = dot4(r1, xa); s2 = dot4(r2, xa);
        s3 = dot4(r3, hv); s4 = dot4(r4, hv); s5 = dot4(r5, hv);
    }
    int lane = tid & 31, w = tid >> 5;
    float v;
    v = warpSum(s0); if (lane == 0) s_red[0 * 8 + w] = v;
    v = warpSum(s1); if (lane == 0) s_red[1 * 8 + w] = v;
    v = warpSum(s2); if (lane == 0) s_red[2 * 8 + w] = v;
    v = warpSum(s3); if (lane == 0) s_red[3 * 8 + w] = v;
    v = warpSum(s4); if (lane == 0) s_red[4 * 8 + w] = v;
    v = warpSum(s5); if (lane == 0) s_red[5 * 8 + w] = v;
    __syncthreads();
    if (tid == 0) {
        float t[6];
#pragma unroll
        for (int i = 0; i < 6; i++) {
            float a = 0.f;
#pragma unroll
            for (int q = 0; q < 8; q++) a += s_red[i * 8 + q];
            t[i] = a;
        }
        float r = 1.f / (1.f + expf(-(t[0] + bih[j] + t[3] + bhh[j])));
        float z = 1.f / (1.f + expf(-(t[1] + bih[HDIM + j] + t[4] + bhh[HDIM + j])));
        float n = tanhf(t[2] + bih[2 * HDIM + j] + r * (t[5] + bhh[2 * HDIM + j]));
        float hnew = (1.f - z) * n + z * hprev[j];
        gout[j] = hnew;
        dout_h[j] = hnew;
    }
    __syncthreads();
}

// ---- mega kernel: GRU0 | GRU1 | energies | softmax+ctx-partial | ctx-reduce ----
__global__ void __launch_bounds__(256, 4) k_mega(
        const int* __restrict__ word, const float* __restrict__ emb,
        const float* __restrict__ last_context, const float* __restrict__ last_hidden,
        const float* __restrict__ enc,
        const float* __restrict__ Wih0, const float* __restrict__ Whh0,
        const float* __restrict__ bih0, const float* __restrict__ bhh0,
        const float* __restrict__ Wih1, const float* __restrict__ Whh1,
        const float* __restrict__ bih1, const float* __restrict__ bhh1,
        float* __restrict__ out_h0, float* __restrict__ out_h1,
        float* __restrict__ out_attn, float* __restrict__ out_ctx) {
    __shared__ float4 s_x[512];     // 8 KB
    __shared__ float4 s_h[256];     // 4 KB
    __shared__ float  s_red[64];
    const int b = blockIdx.x;       // 0..511
    const int tid = threadIdx.x;    // 256
    const int lane = tid & 31, w = tid >> 5;

    // ---------- phase 1: GRU layer 0 (units b and b+512) ----------
    {
        const float4* ew = (const float4*)(emb + (size_t)word[0] * HDIM);
        s_x[tid] = ew[tid];
        s_x[tid + 256] = ((const float4*)last_context)[tid];
        s_h[tid] = ((const float4*)last_hidden)[tid];
        __syncthreads();
        gru_unit<IN0>(b,       tid, Wih0, Whh0, bih0, bhh0, last_hidden, s_x, s_h, s_red, g_h0, out_h0);
        gru_unit<IN0>(b + 512, tid, Wih0, Whh0, bih0, bhh0, last_hidden, s_x, s_h, s_red, g_h0, out_h0);
    }
    gridBarrier(0);

    // ---------- phase 2: GRU layer 1 ----------
    {
        const float* hprev1 = last_hidden + HDIM;
        s_x[tid] = ((const float4*)g_h0)[tid];
        s_h[tid] = ((const float4*)hprev1)[tid];
        __syncthreads();
        gru_unit<HDIM>(b,       tid, Wih1, Whh1, bih1, bhh1, hprev1, s_x, s_h, s_red, g_cat, out_h1);
        gru_unit<HDIM>(b + 512, tid, Wih1, Whh1, bih1, bhh1, hprev1, s_x, s_h, s_red, g_cat, out_h1);
    }
    gridBarrier(1);

    // ---------- phase 3: energies (4 rows per block) + per-block (m,s) ----------
    {
        s_h[tid] = ((const float4*)g_cat)[tid];     // h1
        __syncthreads();
        // warp w: row r = w>>1, half = w&1 (128 float4 per half-row, 4 per lane)
        const int r = w >> 1, half = w & 1;
        const int row = b * 4 + r;
        const float4* e = (const float4*)(enc + (size_t)row * HDIM);
        const int base = half * 128 + lane;
        float4 q0 = s_h[base], q1 = s_h[base + 32], q2 = s_h[base + 64], q3 = s_h[base + 96];
        float4 r0 = __ldcs(e + base), r1 = __ldcs(e + base + 32),
               r2 = __ldcs(e + base + 64), r3 = __ldcs(e + base + 96);
        float acc = dot4(r0, q0) + dot4(r1, q1) + dot4(r2, q2) + dot4(r3, q3);
        acc = warpSum(acc);
        if (lane == 0) s_red[w] = acc;
        __syncthreads();
        if (tid == 0) {
            float E[4];
#pragma unroll
            for (int q = 0; q < 4; q++) {
                E[q] = s_red[2 * q] + s_red[2 * q + 1];
                g_energies[b * 4 + q] = E[q];
            }
            float M = fmaxf(fmaxf(E[0], E[1]), fmaxf(E[2], E[3]));
            float S = expf(E[0] - M) + expf(E[1] - M) + expf(E[2] - M) + expf(E[3] - M);
            g_em[b] = M;
            g_es[b] = S;
        }
    }
    gridBarrier(2);

    // ---------- phase 4: softmax-merge + context partials ----------
    {
        // merge 512 (m,s) partials (2 per thread)
        float M = g_em[tid], S = g_es[tid];
        msMerge(M, S, g_em[tid + 256], g_es[tid + 256]);
#pragma unroll
        for (int o = 16; o > 0; o >>= 1) {
            float M2 = __shfl_down_sync(0xffffffffu, M, o);
            float S2 = __shfl_down_sync(0xffffffffu, S, o);
            msMerge(M, S, M2, S2);
        }
        if (lane == 0) { s_red[w] = M; s_red[8 + w] = S; }
        __syncthreads();
        if (tid == 0) {
            float Mf = s_red[0], Sf = s_red[8];
#pragma unroll
            for (int q = 1; q < 8; q++) msMerge(Mf, Sf, s_red[q], s_red[8 + q]);
            s_red[16] = Mf;
            s_red[17] = 1.f / Sf;
        }
        __syncthreads();
        const float Mg = s_red[16], invS = s_red[17];

        const int bx = b & 3, by = b >> 2;          // 4 h-chunks x 128 s-chunks
        const int s0 = by * (SDIM / SCH);           // 16 rows
        if (tid < SDIM / SCH) {
            float wgt = expf(g_energies[s0 + tid] - Mg) * invS;
            s_red[32 + tid] = wgt;
            if (bx == 0) out_attn[s0 + tid] = wgt;  // scalar store (unaligned dst)
        }
        __syncthreads();
        const int h = bx * 256 + tid;
        const float* e = enc + (size_t)s0 * HDIM + h;
        float r[SDIM / SCH];
#pragma unroll
        for (int i = 0; i < SDIM / SCH; i++) r[i] = __ldcs(e + (size_t)i * HDIM);
        float acc = 0.f;
#pragma unroll
        for (int i = 0; i < SDIM / SCH; i++) acc += s_red[32 + i] * r[i];
        g_ctx_part[by * HDIM + h] = acc;
    }
    gridBarrier(3);

    // ---------- phase 5: context reduce (2 h-values per block) ----------
    {
        const int hh = b * 2 + (tid >> 7);          // h index (0..1023)
        const int p = tid & 127;                    // partial index
        float v = g_ctx_part[(size_t)p * HDIM + hh];
        v = warpSum(v);
        if (lane == 0) s_red[w] = v;
        __syncthreads();
        if ((tid & 127) == 0) {
            int q0 = (tid >> 7) * 4;
            float c = s_red[q0] + s_red[q0 + 1] + s_red[q0 + 2] + s_red[q0 + 3];
            g_cat[HDIM + hh] = c;
            out_ctx[hh] = c;
        }
    }
}

// ---- logits GEMV + per-block (max,sumexp) partial ----
__global__ void __launch_bounds__(256) k_logits(const float* __restrict__ Wout,
                                                const float* __restrict__ bout) {
    __shared__ float4 cs[512];
    __shared__ float sl[8];
    const int tid = threadIdx.x;
    cs[tid] = ((const float4*)g_cat)[tid];
    cs[tid + 256] = ((const float4*)g_cat)[tid + 256];
    __syncthreads();
    const int warp = tid >> 5, lane = tid & 31;
    const int row = blockIdx.x * 8 + warp;
    const bool valid = row < VDIM;
    const int rowc = valid ? row : (VDIM - 1);
    const float4* w4 = (const float4*)(Wout + (size_t)rowc * (2 * HDIM));
    float acc = 0.f;
#pragma unroll
    for (int bq = 0; bq < 2; bq++) {
        float4 r[8];
#pragma unroll
        for (int i = 0; i < 8; i++) r[i] = __ldcs(w4 + bq * 256 + lane + 32 * i);
#pragma unroll
        for (int i = 0; i < 8; i++) acc += dot4(r[i], cs[bq * 256 + lane + 32 * i]);
    }
    acc = warpSum(acc);
    if (lane == 0) {
        float lg = valid ? (acc + bout[row]) : -INFINITY;
        if (valid) g_logits[row] = lg;
        sl[warp] = lg;
    }
    __syncthreads();
    if (tid == 0) {
        float M = sl[0], S = (sl[0] == -INFINITY) ? 0.f : 1.f;
#pragma unroll
        for (int q = 1; q < 8; q++) {
            float lq = sl[q];
            if (lq != -INFINITY) msMerge(M, S, lq, 1.f);
        }
        g_red_m[blockIdx.x] = M;
        g_red_s[blockIdx.x] = S;
    }
}

// ---- k_out: self-reducing lse + write log-softmax ----
__global__ void __launch_bounds__(256) k_out(float* __restrict__ dout) {
    __shared__ float shm[8], shs[8], sh_lse;
    const int tid = threadIdx.x;
    const int lane = tid & 31, w = tid >> 5;
    const int NPT = (NBLK_L + 255) / 256;     // 25
    float rm[NPT], rs[NPT];
#pragma unroll
    for (int k = 0; k < NPT; k++) {
        int i = tid + k * 256;
        bool v = i < NBLK_L;
        rm[k] = v ? g_red_m[i] : -INFINITY;
        rs[k] = v ? g_red_s[i] : 0.f;
    }
    float M = rm[0], S = rs[0];
#pragma unroll
    for (int k = 1; k < NPT; k++) msMerge(M, S, rm[k], rs[k]);
#pragma unroll
    for (int o = 16; o > 0; o >>= 1) {
        float M2 = __shfl_down_sync(0xffffffffu, M, o);
        float S2 = __shfl_down_sync(0xffffffffu, S, o);
        msMerge(M, S, M2, S2);
    }
    if (lane == 0) { shm[w] = M; shs[w] = S; }
    __syncthreads();
    if (tid == 0) {
        float Mf = shm[0], Sf = shs[0];
#pragma unroll
        for (int q = 1; q < 8; q++) msMerge(Mf, Sf, shm[q], shs[q]);
        sh_lse = Mf + logf(Sf);
    }
    __syncthreads();
    float lse = sh_lse;
    int v = blockIdx.x * 256 + tid;
    if (v < VDIM) dout[v] = g_logits[v] - lse;
}

extern "C" void kernel_launch(void* const* d_in, const int* in_sizes, int n_in,
                              void* d_out, int out_size) {
    const int*   word         = (const int*)d_in[0];
    const float* last_context = (const float*)d_in[1];
    const float* last_hidden  = (const float*)d_in[2];   // (2,1,H)
    const float* enc          = (const float*)d_in[3];   // (S,1,H)
    const float* emb  = (const float*)d_in[4];
    const float* Wih0 = (const float*)d_in[5];
    const float* Whh0 = (const float*)d_in[6];
    const float* bih0 = (const float*)d_in[7];
    const float* bhh0 = (const float*)d_in[8];
    const float* Wih1 = (const float*)d_in[9];
    const float* Whh1 = (const float*)d_in[10];
    const float* bih1 = (const float*)d_in[11];
    const float* bhh1 = (const float*)d_in[12];
    const float* Wout = (const float*)d_in[13];
    const float* bout = (const float*)d_in[14];

    float* out       = (float*)d_out;
    float* out_ctx   = out + VDIM;
    float* out_h0    = out + VDIM + HDIM;
    float* out_h1    = out + VDIM + 2 * HDIM;
    float* out_attn  = out + VDIM + 3 * HDIM;

    k_mega<<<NMEGA, 256>>>(word, emb, last_context, last_hidden, enc,
                           Wih0, Whh0, bih0, bhh0, Wih1, Whh1, bih1, bhh1,
                           out_h0, out_h1, out_attn, out_ctx);
    k_logits<<<NBLK_L, 256>>>(Wout, bout);
    k_out<<<(VDIM + 255) / 256, 256>>>(out);
}